// round 14
// baseline (speedup 1.0000x reference)
#include <cuda_runtime.h>
#include <cuda_bf16.h>
#include <mma.h>
#include <cstdint>

using namespace nvcuda;

// Problem constants (fixed by dataset: N_NODES=1M, D_IN=D_HID=64, 10 ratings)
#define MAX_E  1000000
#define NR     10
#define D      64
#define TILE   128                 // rows per CTA tile (8 warps x 16 rows)
#define CPR    29                  // CTAs per rating (10*29 = 290 <= 296 slots)
#define TPB    256

#define LDA    72                  // bf16 elems per A/W row (pad kills conflicts)
#define LDE    68                  // f32 elems per epilogue row

// ---- kernel-3 SMEM layout (byte offsets) ----
#define OFF_NODE 0                          // 128 x int
#define OFF_INVC 512                        // 128 x float
#define OFF_WHI  1024                       // 64 x LDA bf16 = 9216 B
#define OFF_WLO  (OFF_WHI + 9216)
#define OFF_A    (OFF_WLO + 9216)           // Ahi/Alo: 128 x LDA bf16 each
#define OFF_AHI  OFF_A
#define OFF_ALO  (OFF_A + 18432)
#define OFF_EPI  OFF_A                      // f32 128 x LDE (aliases dead A tiles)
#define SMEM_TOTAL (OFF_A + 2 * 18432)      // 56320 B

static __device__ __forceinline__ uint32_t packbf(float lo, float hi) {
    uint32_t r;
    asm("cvt.rn.bf16x2.f32 %0, %1, %2;" : "=r"(r) : "f"(hi), "f"(lo));
    return r;
}

// ---------------- static device scratch (no runtime allocation) ----------------
__device__ int   g_bin_count[NR];
__device__ int   g_is64;
__device__ int   g_node_buf[NR * MAX_E];
__device__ float g_invc_buf[NR * MAX_E];

// ---------------- kernel 1: reset counters + detect index dtype ----------------
__global__ void init_kernel(const int* __restrict__ rating_as_i32, int E) {
    int t = threadIdx.x;
    if (t < NR) g_bin_count[t] = 0;
    int probe = (t < 32 && (2 * t + 1) < E) ? rating_as_i32[2 * t + 1] : 0;
    unsigned all_zero = __ballot_sync(0xFFFFFFFFu, probe == 0);
    if (t == 0) g_is64 = (all_zero == 0xFFFFFFFFu) ? 1 : 0;
}

// ---------------- kernel 2: bucket rows by rating ----------------
__global__ void bucket_scatter_kernel(const void*  __restrict__ edge_node,
                                      const void*  __restrict__ edge_rating,
                                      const float* __restrict__ inv_c,
                                      int E) {
    __shared__ int s_cnt[NR];
    __shared__ int s_base[NR];
    __shared__ int s_off[NR];
    int t = threadIdx.x;
    if (t < NR) { s_cnt[t] = 0; s_off[t] = 0; }
    __syncthreads();

    const int is64 = g_is64;
    const int*       rat32 = (const int*)edge_rating;
    const long long* rat64 = (const long long*)edge_rating;
    const int*       nod32 = (const int*)edge_node;
    const long long* nod64 = (const long long*)edge_node;

    int chunk = (E + gridDim.x - 1) / gridDim.x;
    int start = blockIdx.x * chunk;
    int end   = min(start + chunk, E);

    #pragma unroll 4
    for (int e = start + t; e < end; e += blockDim.x) {
        int r = is64 ? (int)rat64[e] : rat32[e];
        r = min(max(r, 0), NR - 1);
        atomicAdd(&s_cnt[r], 1);
    }
    __syncthreads();
    if (t < NR) s_base[t] = atomicAdd(&g_bin_count[t], s_cnt[t]);
    __syncthreads();
    #pragma unroll 4
    for (int e = start + t; e < end; e += blockDim.x) {
        int r = is64 ? (int)rat64[e] : rat32[e];
        r = min(max(r, 0), NR - 1);
        int pos = s_base[r] + atomicAdd(&s_off[r], 1);
        pos = min(pos, MAX_E - 1);
        g_node_buf[r * MAX_E + pos] = is64 ? (int)nod64[e] : nod32[e];
        g_invc_buf[r * MAX_E + pos] = inv_c[e];
    }
}

// ---------------- kernel 3: rating-grouped GEMM on WMMA (3xBF16 split) ----------------
// tcgen05 is unavailable (harness targets baseline sm_100), so use the portable
// wmma path (HMMA): per 128-row tile, gather x rows with on-the-fly
// f32 -> (bf16_hi, bf16_lo) split into padded SMEM tiles, then each warp does
// 16 rows x 64 cols via m16n16k16 bf16 MMAs: xh*Wh + xh*Wl + xl*Wh with fp32
// accumulators (rel err ~1.5e-5). W[j][k] is used directly as a col-major B
// operand (no transpose needed). Epilogue f32 buffer aliases the dead A tiles;
// scale by inv_c happens during the cooperative coalesced scatter.
extern __shared__ char s_raw[];

__global__ __launch_bounds__(TPB, 2)
void rating_wmma_kernel(const float* __restrict__ embed,
                        const float* __restrict__ weights,
                        float*       __restrict__ out,
                        int n_nodes) {
    int tid  = threadIdx.x;
    int wid  = tid >> 5;
    int lane = tid & 31;

    int*   s_node = (int*)(s_raw + OFF_NODE);
    float* s_invc = (float*)(s_raw + OFF_INVC);
    __nv_bfloat16* s_wh = (__nv_bfloat16*)(s_raw + OFF_WHI);
    __nv_bfloat16* s_wl = (__nv_bfloat16*)(s_raw + OFF_WLO);
    __nv_bfloat16* s_ah = (__nv_bfloat16*)(s_raw + OFF_AHI);
    __nv_bfloat16* s_al = (__nv_bfloat16*)(s_raw + OFF_ALO);
    float*         s_ep = (float*)(s_raw + OFF_EPI);

    int r   = blockIdx.x / CPR;
    int cta = blockIdx.x % CPR;
    int roff = r * MAX_E;

    // One-time weight split: W[r] (64x64 f32) -> bf16 hi/lo padded tiles
    const float* wsrc = weights + r * D * D;
    for (int g = tid; g < 1024; g += TPB) {          // 64 rows x 16 float4 chunks
        int j = g >> 4, c = g & 15;
        float4 v = ((const float4*)(wsrc + j * D))[c];
        uint32_t h0 = packbf(v.x, v.y), h1 = packbf(v.z, v.w);
        float r0 = v.x - __uint_as_float(h0 << 16);
        float r1 = v.y - __uint_as_float(h0 & 0xFFFF0000u);
        float r2 = v.z - __uint_as_float(h1 << 16);
        float r3 = v.w - __uint_as_float(h1 & 0xFFFF0000u);
        uint32_t l0 = packbf(r0, r1), l1 = packbf(r2, r3);
        *(uint2*)(s_wh + j * LDA + c * 4) = make_uint2(h0, h1);
        *(uint2*)(s_wl + j * LDA + c * 4) = make_uint2(l0, l1);
    }

    int cnt    = min(g_bin_count[r], MAX_E);
    int nTiles = (cnt + TILE - 1) / TILE;

    for (int tile = cta; tile < nTiles; tile += CPR) {
        int tb = tile * TILE;
        __syncthreads();                              // guard reused A/epi smem
        if (tid < TILE) {
            int s   = tb + tid;
            int idx = min(s, cnt - 1);
            int nd  = g_node_buf[roff + idx];
            s_node[tid] = min(max(nd, 0), n_nodes - 1);
            s_invc[tid] = (s < cnt) ? g_invc_buf[roff + idx] : 0.f;
        }
        __syncthreads();

        // gather + f32->bf16 split: 2048 float4 chunks (128 rows x 16)
        for (int g = tid; g < 2048; g += TPB) {
            int row = g >> 4, c = g & 15;
            int nd = s_node[row];
            float4 v = ((const float4*)(embed + (size_t)nd * D))[c];
            uint32_t h0 = packbf(v.x, v.y), h1 = packbf(v.z, v.w);
            float r0 = v.x - __uint_as_float(h0 << 16);
            float r1 = v.y - __uint_as_float(h0 & 0xFFFF0000u);
            float r2 = v.z - __uint_as_float(h1 << 16);
            float r3 = v.w - __uint_as_float(h1 & 0xFFFF0000u);
            uint32_t l0 = packbf(r0, r1), l1 = packbf(r2, r3);
            *(uint2*)(s_ah + row * LDA + c * 4) = make_uint2(h0, h1);
            *(uint2*)(s_al + row * LDA + c * 4) = make_uint2(l0, l1);
        }
        __syncthreads();

        // MMA: warp handles rows [wid*16, wid*16+16), all 64 cols
        wmma::fragment<wmma::accumulator, 16, 16, 16, float> fc[4];
        #pragma unroll
        for (int nt = 0; nt < 4; ++nt) wmma::fill_fragment(fc[nt], 0.0f);

        const __nv_bfloat16* apass[3] = { s_ah, s_ah, s_al };
        const __nv_bfloat16* bpass[3] = { s_wh, s_wl, s_wh };
        #pragma unroll
        for (int p = 0; p < 3; ++p) {
            const __nv_bfloat16* abase = apass[p] + wid * 16 * LDA;
            const __nv_bfloat16* bbase = bpass[p];
            #pragma unroll
            for (int kt = 0; kt < 4; ++kt) {
                wmma::fragment<wmma::matrix_a, 16, 16, 16, __nv_bfloat16,
                               wmma::row_major> fa;
                wmma::load_matrix_sync(fa, abase + kt * 16, LDA);
                #pragma unroll
                for (int nt = 0; nt < 4; ++nt) {
                    wmma::fragment<wmma::matrix_b, 16, 16, 16, __nv_bfloat16,
                                   wmma::col_major> fb;
                    // W[j][k] row-major == B col-major (k,n) with ld = LDA
                    wmma::load_matrix_sync(fb, bbase + (nt * 16) * LDA + kt * 16,
                                           LDA);
                    wmma::mma_sync(fc[nt], fa, fb, fc[nt]);
                }
            }
        }
        __syncthreads();                              // A tiles dead -> epi alias

        #pragma unroll
        for (int nt = 0; nt < 4; ++nt)
            wmma::store_matrix_sync(s_ep + (wid * 16) * LDE + nt * 16, fc[nt],
                                    LDE, wmma::mem_row_major);
        __syncthreads();

        // cooperative scatter (scale by inv_c here): instr covers 2 rows
        for (int i = wid; i < 64; i += 8) {
            int row = 2 * i + (lane >> 4);
            int c   = lane & 15;
            if (tb + row < cnt) {
                float ic = s_invc[row];
                float4 v = *(float4*)(s_ep + row * LDE + 4 * c);
                v.x *= ic; v.y *= ic; v.z *= ic; v.w *= ic;
                ((float4*)(out + (size_t)s_node[row] * D))[c] = v;
            }
        }
    }
}

// ---------------- launch ----------------
extern "C" void kernel_launch(void* const* d_in, const int* in_sizes, int n_in,
                              void* d_out, int out_size) {
    const float* embed       = (const float*)d_in[0];
    const float* weights     = (const float*)d_in[1];
    const float* inv_c       = (const float*)d_in[2];
    const void*  edge_node   = d_in[3];
    const void*  edge_rating = d_in[4];
    int E       = in_sizes[3];
    int n_nodes = out_size / D;

    (void)cudaFuncSetAttribute(rating_wmma_kernel,
                               cudaFuncAttributeMaxDynamicSharedMemorySize,
                               SMEM_TOTAL);

    init_kernel<<<1, 32>>>((const int*)edge_rating, E);
    bucket_scatter_kernel<<<512, 256>>>(edge_node, edge_rating, inv_c, E);
    rating_wmma_kernel<<<NR * CPR, TPB, SMEM_TOTAL>>>(embed, weights,
                                                      (float*)d_out, n_nodes);
}